// round 14
// baseline (speedup 1.0000x reference)
#include <cuda_runtime.h>
#include <cuda_fp16.h>
#include <stdint.h>

// ===========================================================================
// 5-layer masked MLP, fp16 mma.sync.m16n8k16 (fp32 accum), fragment-permuted
// packed operands. BM=128, BN=128, BK=64, 256 thr (8 warps 2m x 4n),
// warp tile 64x32. 3-stage cp.async ring, 2 CTAs/SM.
// R13: ONE __syncthreads per k-step (trailing barrier proven redundant),
//      wrap-increment stage counters. Otherwise identical to 588us champion.
// ===========================================================================

#define NTHREADS 256
#define STAGE_BYTES 32768u           // A 16KB + B 16KB (128x64 fp16 each)
#define SMEM_REQ (3 * 32768)

// ---- device scratch ----
__device__ uint32_t g_Apack0[16777216];   // 32768 x 1024 fp16 (as fp16x2 words)
__device__ uint32_t g_Apack1[16777216];
// W pack tiles: 128n x 64k fp16 = 4096 words each, [ntile][ktile]
__device__ uint32_t g_Wpack[1339392];
#define WOFF1 0
#define WOFF2 524288
#define WOFF3 983040
#define WOFF4 1196032

// ---------------------------------------------------------------------------
__device__ __forceinline__ uint32_t smem_u32(const void* p) {
    uint32_t a;
    asm("{ .reg .u64 t; cvta.to.shared.u64 t, %1; cvt.u32.u64 %0, t; }" : "=r"(a) : "l"(p));
    return a;
}
__device__ __forceinline__ void cpa16(uint32_t saddr, const void* g) {
    asm volatile("cp.async.cg.shared.global [%0], [%1], 16;" :: "r"(saddr), "l"(g));
}
#define CPA_COMMIT() asm volatile("cp.async.commit_group;" ::: "memory")
#define CPA_WAIT1()  asm volatile("cp.async.wait_group 1;" ::: "memory")

__device__ __forceinline__ void mma_f16(float* c,
                                        uint32_t a0, uint32_t a1, uint32_t a2, uint32_t a3,
                                        uint32_t b0, uint32_t b1) {
    asm volatile("mma.sync.aligned.m16n8k16.row.col.f32.f16.f16.f32 "
                 "{%0,%1,%2,%3}, {%4,%5,%6,%7}, {%8,%9}, {%0,%1,%2,%3};"
                 : "+f"(c[0]), "+f"(c[1]), "+f"(c[2]), "+f"(c[3])
                 : "r"(a0), "r"(a1), "r"(a2), "r"(a3), "r"(b0), "r"(b1));
}

__device__ __forceinline__ uint32_t pack_half2(float lo, float hi) {
    __half2 h = __floats2half2_rn(lo, hi);
    return *(uint32_t*)&h;
}

// A-pack word index for element pair (row r, cols c..c+1), c even.
// Tile (128r x 64k) = 4096 words: [frag8*4+kk][lane32][word4]
__device__ __forceinline__ size_t wordA(int r, int c, int T) {
    int mtile = r >> 7, frag = (r >> 4) & 7, g = r & 7, half = (r >> 3) & 1;
    int kt = c >> 6, kloc = c & 63, kk = kloc >> 4, k16 = kloc & 15;
    int khi = k16 >> 3, t = (k16 >> 1) & 3;
    return (((size_t)(mtile * T + kt)) << 12)
         + (size_t)(((frag * 4 + kk) * 32 + 4 * g + t) * 4 + half + 2 * khi);
}
// W-pack word index for (n, cols c..c+1). Tile 4096 words: [nj16*4+kk][lane32][word2]
__device__ __forceinline__ size_t wordW(int n, int c, int T) {
    int ntile = n >> 7, nj = (n >> 3) & 15, g = n & 7;
    int kt = c >> 6, kloc = c & 63, kk = kloc >> 4, k16 = kloc & 15;
    int khi = k16 >> 3, t = (k16 >> 1) & 3;
    return (((size_t)(ntile * T + kt)) << 12)
         + (size_t)(((nj * 4 + kk) * 32 + 4 * g + t) * 2 + khi);
}

// ---------------------------------------------------------------------------
// Merged prep: pack masked weights of all 4 layers (blockIdx.y = layer).
// ---------------------------------------------------------------------------
struct WArgs { const float* W; const uint32_t* M; uint32_t* out; int N, K, Kpad, nTiles; };

__global__ void wpack_all_kernel(WArgs a0, WArgs a1, WArgs a2, WArgs a3)
{
    WArgs A;
    switch (blockIdx.y) {
        case 0: A = a0; break;
        case 1: A = a1; break;
        case 2: A = a2; break;
        default: A = a3; break;
    }
    const int T = A.Kpad >> 6;
    const int Kp2 = A.Kpad >> 1;
    size_t total = (size_t)A.nTiles * 128 * Kp2;
    for (size_t idx = (size_t)blockIdx.x * blockDim.x + threadIdx.x; idx < total;
         idx += (size_t)gridDim.x * blockDim.x) {
        int n = (int)(idx / Kp2);
        int c = (int)(idx % Kp2) * 2;
        float lo = 0.f, hi = 0.f;
        if (n < A.N) {
            size_t off = (size_t)n * A.K + c;
            if (c < A.K     && A.M[off]     != 0u) lo = A.W[off];
            if (c + 1 < A.K && A.M[off + 1] != 0u) hi = A.W[off + 1];
        }
        A.out[wordW(n, c, T)] = pack_half2(lo, hi);
    }
}

// Prep: pack x [32768,1024] fp32 -> fp16 pack. One float4 per thread.
__global__ void xpack_kernel(const float* __restrict__ X, uint32_t* __restrict__ out)
{
    const int K = 1024, T = 16;
    int idx = blockIdx.x * blockDim.x + threadIdx.x;
    int kc = idx & 255, r = idx >> 8;
    int k = kc * 4;
    float4 v = *(const float4*)&X[(size_t)r * K + k];
    size_t w0 = wordA(r, k, T);          // pair (k, k+1)
    out[w0]     = pack_half2(v.x, v.y);
    out[w0 + 4] = pack_half2(v.z, v.w);  // pair (k+2, k+3): t -> t+1 = +4 words
}

// ---------------------------------------------------------------------------
// Main GEMM: C = act(Apack @ Wpack^T + bias); emits fp16 pack of C.
// Single barrier per k-step; 3-stage ring with wrap counters.
// ---------------------------------------------------------------------------
__global__ __launch_bounds__(NTHREADS, 2)
void mma_layer_kernel(const uint32_t* __restrict__ Ap, const uint32_t* __restrict__ Wp,
                      const float* __restrict__ bias, float* __restrict__ C,
                      uint32_t* __restrict__ packOut,
                      int N, int T, int Tn, int KpadNext, int doRelu)
{
    extern __shared__ uint32_t dynsmem[];
    const uint32_t sbase = smem_u32(dynsmem);

    const int tid    = threadIdx.x;
    const int warp   = tid >> 5;
    const int lane   = tid & 31;
    const int warp_n = warp & 3;
    const int warp_m = warp >> 2;
    const int g      = lane >> 2;
    const int t      = lane & 3;
    const int mtile  = blockIdx.y;
    const int ntile  = blockIdx.x;
    const int m0     = mtile << 7;
    const int n0     = ntile << 7;

    const uint32_t* aSrc = Ap + ((size_t)mtile * T << 12);
    const uint32_t* wSrc = Wp + ((size_t)ntile * T << 12);

    float acc[4][4][4];
    #pragma unroll
    for (int i = 0; i < 4; i++)
        #pragma unroll
        for (int j = 0; j < 4; j++)
            #pragma unroll
            for (int q = 0; q < 4; q++) acc[i][j][q] = 0.f;

    auto issue = [&](int s, int kb) {
        uint32_t ab = sbase + (uint32_t)s * STAGE_BYTES;
        uint32_t wb = ab + 16384u;
        const uint32_t* a = aSrc + ((size_t)kb << 12);
        const uint32_t* w = wSrc + ((size_t)kb << 12);
        #pragma unroll
        for (int j = 0; j < 4; j++) {
            int o = tid + j * 256;
            cpa16(ab + o * 16u, a + o * 4);
            cpa16(wb + o * 16u, w + o * 4);
        }
        CPA_COMMIT();
    };

    issue(0, 0);
    if (T > 1) issue(1, 1);

    int sCur = 0;          // stage being computed this iteration
    int sNxt = 2;          // stage the producer fills this iteration
    for (int kb = 0; kb < T; kb++) {
        CPA_WAIT1();
        __syncthreads();                       // publishes stage sCur; also
                                               // guarantees all reads of sNxt
                                               // (done at kb-1) are complete
        if (kb + 2 < T) issue(sNxt, kb + 2);

        const uint32_t ab = sbase + (uint32_t)sCur * STAGE_BYTES;
        const uint32_t wb = ab + 16384u;

        #pragma unroll
        for (int kk = 0; kk < 4; kk++) {
            uint32_t a[4][4], b[4][2];
            #pragma unroll
            for (int mi = 0; mi < 4; mi++) {
                int frag = warp_m * 4 + mi;
                uint32_t addr = ab + (uint32_t)(((frag * 4 + kk) * 32 + lane) * 16);
                asm volatile("ld.shared.v4.u32 {%0,%1,%2,%3}, [%4];"
                             : "=r"(a[mi][0]), "=r"(a[mi][1]), "=r"(a[mi][2]), "=r"(a[mi][3])
                             : "r"(addr));
            }
            #pragma unroll
            for (int nj = 0; nj < 4; nj++) {
                int njg = warp_n * 4 + nj;
                uint32_t addr = wb + (uint32_t)((((njg * 4 + kk) * 32) + lane) * 8);
                asm volatile("ld.shared.v2.u32 {%0,%1}, [%2];"
                             : "=r"(b[nj][0]), "=r"(b[nj][1]) : "r"(addr));
            }
            #pragma unroll
            for (int mi = 0; mi < 4; mi++)
                #pragma unroll
                for (int nj = 0; nj < 4; nj++)
                    mma_f16(acc[mi][nj], a[mi][0], a[mi][1], a[mi][2], a[mi][3],
                            b[nj][0], b[nj][1]);
        }
        // no trailing barrier: next iteration's top barrier orders the ring
        sCur = (sCur == 2) ? 0 : sCur + 1;
        sNxt = (sNxt == 2) ? 0 : sNxt + 1;
    }

    // ---- epilogue: bias + relu -> C (fp32), fp16 pack -> next layer ----
    #pragma unroll
    for (int mi = 0; mi < 4; mi++) {
        int r0 = m0 + warp_m * 64 + mi * 16 + g;
        #pragma unroll
        for (int nj = 0; nj < 4; nj++) {
            int cb = n0 + warp_n * 32 + nj * 8 + t * 2;
            float v0 = acc[mi][nj][0], v1 = acc[mi][nj][1];
            float v2 = acc[mi][nj][2], v3 = acc[mi][nj][3];
            if (cb < N) {     // N even -> cb+1 < N too
                float b0 = bias[cb], b1 = bias[cb + 1];
                v0 += b0; v1 += b1; v2 += b0; v3 += b1;
                if (doRelu) {
                    v0 = fmaxf(v0, 0.f); v1 = fmaxf(v1, 0.f);
                    v2 = fmaxf(v2, 0.f); v3 = fmaxf(v3, 0.f);
                }
                *(float2*)&C[(size_t)r0 * N + cb]       = make_float2(v0, v1);
                *(float2*)&C[(size_t)(r0 + 8) * N + cb] = make_float2(v2, v3);
            } else { v0 = v1 = v2 = v3 = 0.f; }
            if (packOut && cb < KpadNext) {
                packOut[wordA(r0,     cb, Tn)] = pack_half2(v0, v1);
                packOut[wordA(r0 + 8, cb, Tn)] = pack_half2(v2, v3);
            }
        }
    }
}

// ---------------------------------------------------------------------------
// Layer 5: [B,600] -> [B,6] GEMV, warp per row, writes both h5 slots.
// ---------------------------------------------------------------------------
__global__ __launch_bounds__(256)
void final_layer_kernel(const float* __restrict__ A, const float* __restrict__ W,
                        const uint32_t* __restrict__ Msk, const float* __restrict__ bias,
                        float* __restrict__ O1, float* __restrict__ O2, int K)
{
    __shared__ float ws[600 * 6];
    const int tid = threadIdx.x;
    for (int idx = tid; idx < K * 6; idx += 256) {
        int n = idx / K, k = idx % K;
        size_t off = (size_t)n * K + k;
        ws[k * 6 + n] = (Msk[off] != 0u) ? W[off] : 0.0f;
    }
    __syncthreads();

    const int warp = tid >> 5, lane = tid & 31;
    const int row  = blockIdx.x * 8 + warp;
    const float* a = &A[(size_t)row * K];

    float acc[6] = {0.f, 0.f, 0.f, 0.f, 0.f, 0.f};
    for (int k = lane; k < K; k += 32) {
        float av = a[k];
        #pragma unroll
        for (int j = 0; j < 6; j++) acc[j] = fmaf(av, ws[k * 6 + j], acc[j]);
    }
    #pragma unroll
    for (int j = 0; j < 6; j++)
        #pragma unroll
        for (int o = 16; o > 0; o >>= 1)
            acc[j] += __shfl_xor_sync(0xffffffffu, acc[j], o);
    if (lane == 0) {
        #pragma unroll
        for (int j = 0; j < 6; j++) {
            float v = acc[j] + bias[j];
            O1[(size_t)row * 6 + j] = v;
            O2[(size_t)row * 6 + j] = v;
        }
    }
}

// ---------------------------------------------------------------------------
extern "C" void kernel_launch(void* const* d_in, const int* in_sizes, int n_in,
                              void* d_out, int out_size)
{
    (void)in_sizes; (void)n_in; (void)out_size;
    const int B = 32768;

    const float*    x  = (const float*)d_in[0];
    const float*    W1 = (const float*)d_in[1];
    const float*    b1 = (const float*)d_in[2];
    const uint32_t* m1 = (const uint32_t*)d_in[3];
    const float*    W2 = (const float*)d_in[4];
    const float*    b2 = (const float*)d_in[5];
    const uint32_t* m2 = (const uint32_t*)d_in[6];
    const float*    W3 = (const float*)d_in[7];
    const float*    b3 = (const float*)d_in[8];
    const uint32_t* m3 = (const uint32_t*)d_in[9];
    const float*    W4 = (const float*)d_in[10];
    const float*    b4 = (const float*)d_in[11];
    const uint32_t* m4 = (const uint32_t*)d_in[12];
    const float*    W5 = (const float*)d_in[13];
    const float*    b5 = (const float*)d_in[14];
    const uint32_t* m5 = (const uint32_t*)d_in[15];

    float* out = (float*)d_out;
    float* h5a = out;                    // [B,6]
    float* h1  = out + (size_t)B * 6;    // [B,1000]
    float* h2  = h1  + (size_t)B * 1000; // [B,800]
    float* h3  = h2  + (size_t)B * 800;  // [B,400]
    float* h4  = h3  + (size_t)B * 400;  // [B,600]
    float* h5b = h4  + (size_t)B * 600;  // [B,6]

    uint32_t *ap0, *ap1, *wp;
    cudaGetSymbolAddress((void**)&ap0, g_Apack0);
    cudaGetSymbolAddress((void**)&ap1, g_Apack1);
    cudaGetSymbolAddress((void**)&wp,  g_Wpack);

    static bool attrDone = false;
    if (!attrDone) {
        cudaFuncSetAttribute(mma_layer_kernel, cudaFuncAttributeMaxDynamicSharedMemorySize, SMEM_REQ);
        attrDone = true;
    }

    // ---- prep: pack all weights in ONE launch, then x ----
    WArgs wa1 = { W1, m1, wp + WOFF1, 1000, 1024, 1024, 8 };
    WArgs wa2 = { W2, m2, wp + WOFF2,  800, 1000, 1024, 7 };
    WArgs wa3 = { W3, m3, wp + WOFF3,  400,  800,  832, 4 };
    WArgs wa4 = { W4, m4, wp + WOFF4,  600,  400,  448, 5 };
    wpack_all_kernel<<<dim3(384, 4), 256>>>(wa1, wa2, wa3, wa4);
    xpack_kernel<<<B, 256>>>(x, ap0);

    dim3 blk(NTHREADS);
    const int SM = SMEM_REQ;
    // L1: Kpad=1024 (T=16) -> h1 [B,1000]; pack -> ap1 (KpadNext=1024, Tn=16)
    mma_layer_kernel<<<dim3(8, B/128), blk, SM>>>(ap0, wp + WOFF1, b1, h1, ap1, 1000, 16, 16, 1024, 1);
    // L2: Kpad=1024 (T=16) -> h2 [B,800]; pack -> ap0 (KpadNext=832, Tn=13)
    mma_layer_kernel<<<dim3(7, B/128), blk, SM>>>(ap1, wp + WOFF2, b2, h2, ap0,  800, 16, 13,  832, 1);
    // L3: Kpad=832 (T=13) -> h3 [B,400]; pack -> ap1 (KpadNext=448, Tn=7)
    mma_layer_kernel<<<dim3(4, B/128), blk, SM>>>(ap0, wp + WOFF3, b3, h3, ap1,  400, 13,  7,  448, 1);
    // L4: Kpad=448 (T=7) -> h4 [B,600]; no pack, no relu
    mma_layer_kernel<<<dim3(5, B/128), blk, SM>>>(ap1, wp + WOFF4, b4, h4, (uint32_t*)0, 600, 7, 0, 0, 0);
    // L5 GEMV
    final_layer_kernel<<<B/8, 256>>>(h4, W5, m5, b5, h5a, h5b, 600);
}

// round 15
// speedup vs baseline: 1.4778x; 1.4778x over previous
#include <cuda_runtime.h>
#include <cuda_fp16.h>
#include <stdint.h>

// ===========================================================================
// 5-layer masked MLP, fp16 mma.sync.m16n8k16 (fp32 accum), fragment-permuted
// packed operands. BM=128, BN=128, BK=64, 256 thr (8 warps 2m x 4n),
// warp tile 64x32. 3-stage cp.async ring, TWO barriers per k-step
// (phase-locking measured faster), 2 CTAs/SM.  == 588us champion mainloop ==
// R15 adds: prepacked masked W5 + 16-row GEMV blocks.
// ===========================================================================

#define NTHREADS 256
#define STAGE_BYTES 32768u           // A 16KB + B 16KB (128x64 fp16 each)
#define SMEM_REQ (3 * 32768)

// ---- device scratch ----
__device__ uint32_t g_Apack0[16777216];   // 32768 x 1024 fp16 (as fp16x2 words)
__device__ uint32_t g_Apack1[16777216];
__device__ uint32_t g_Wpack[1339392];     // fragment-permuted W tiles, 4 layers
__device__ float    g_W5pack[3600];       // masked W5, ws[k*6+n]
#define WOFF1 0
#define WOFF2 524288
#define WOFF3 983040
#define WOFF4 1196032

// ---------------------------------------------------------------------------
__device__ __forceinline__ uint32_t smem_u32(const void* p) {
    uint32_t a;
    asm("{ .reg .u64 t; cvta.to.shared.u64 t, %1; cvt.u32.u64 %0, t; }" : "=r"(a) : "l"(p));
    return a;
}
__device__ __forceinline__ void cpa16(uint32_t saddr, const void* g) {
    asm volatile("cp.async.cg.shared.global [%0], [%1], 16;" :: "r"(saddr), "l"(g));
}
#define CPA_COMMIT() asm volatile("cp.async.commit_group;" ::: "memory")
#define CPA_WAIT1()  asm volatile("cp.async.wait_group 1;" ::: "memory")

__device__ __forceinline__ void mma_f16(float* c,
                                        uint32_t a0, uint32_t a1, uint32_t a2, uint32_t a3,
                                        uint32_t b0, uint32_t b1) {
    asm volatile("mma.sync.aligned.m16n8k16.row.col.f32.f16.f16.f32 "
                 "{%0,%1,%2,%3}, {%4,%5,%6,%7}, {%8,%9}, {%0,%1,%2,%3};"
                 : "+f"(c[0]), "+f"(c[1]), "+f"(c[2]), "+f"(c[3])
                 : "r"(a0), "r"(a1), "r"(a2), "r"(a3), "r"(b0), "r"(b1));
}

__device__ __forceinline__ uint32_t pack_half2(float lo, float hi) {
    __half2 h = __floats2half2_rn(lo, hi);
    return *(uint32_t*)&h;
}

// A-pack word index for element pair (row r, cols c..c+1), c even.
// Tile (128r x 64k) = 4096 words: [frag8*4+kk][lane32][word4]
__device__ __forceinline__ size_t wordA(int r, int c, int T) {
    int mtile = r >> 7, frag = (r >> 4) & 7, g = r & 7, half = (r >> 3) & 1;
    int kt = c >> 6, kloc = c & 63, kk = kloc >> 4, k16 = kloc & 15;
    int khi = k16 >> 3, t = (k16 >> 1) & 3;
    return (((size_t)(mtile * T + kt)) << 12)
         + (size_t)(((frag * 4 + kk) * 32 + 4 * g + t) * 4 + half + 2 * khi);
}
// W-pack word index for (n, cols c..c+1). Tile 4096 words: [nj16*4+kk][lane32][word2]
__device__ __forceinline__ size_t wordW(int n, int c, int T) {
    int ntile = n >> 7, nj = (n >> 3) & 15, g = n & 7;
    int kt = c >> 6, kloc = c & 63, kk = kloc >> 4, k16 = kloc & 15;
    int khi = k16 >> 3, t = (k16 >> 1) & 3;
    return (((size_t)(ntile * T + kt)) << 12)
         + (size_t)(((nj * 4 + kk) * 32 + 4 * g + t) * 2 + khi);
}

// ---------------------------------------------------------------------------
// Merged prep: pack masked weights of layers 1-4 (blockIdx.y = layer) and
// masked W5 (blockIdx.y == 4).
// ---------------------------------------------------------------------------
struct WArgs { const float* W; const uint32_t* M; uint32_t* out; int N, K, Kpad, nTiles; };

__global__ void wpack_all_kernel(WArgs a0, WArgs a1, WArgs a2, WArgs a3,
                                 const float* __restrict__ W5,
                                 const uint32_t* __restrict__ m5)
{
    if (blockIdx.y == 4) {
        // masked W5 -> g_W5pack[k*6+n]
        for (int idx = blockIdx.x * blockDim.x + threadIdx.x; idx < 600 * 6;
             idx += gridDim.x * blockDim.x) {
            int n = idx / 600, k = idx % 600;
            size_t off = (size_t)n * 600 + k;
            g_W5pack[k * 6 + n] = (m5[off] != 0u) ? W5[off] : 0.0f;
        }
        return;
    }
    WArgs A;
    switch (blockIdx.y) {
        case 0: A = a0; break;
        case 1: A = a1; break;
        case 2: A = a2; break;
        default: A = a3; break;
    }
    const int T = A.Kpad >> 6;
    const int Kp2 = A.Kpad >> 1;
    size_t total = (size_t)A.nTiles * 128 * Kp2;
    for (size_t idx = (size_t)blockIdx.x * blockDim.x + threadIdx.x; idx < total;
         idx += (size_t)gridDim.x * blockDim.x) {
        int n = (int)(idx / Kp2);
        int c = (int)(idx % Kp2) * 2;
        float lo = 0.f, hi = 0.f;
        if (n < A.N) {
            size_t off = (size_t)n * A.K + c;
            if (c < A.K     && A.M[off]     != 0u) lo = A.W[off];
            if (c + 1 < A.K && A.M[off + 1] != 0u) hi = A.W[off + 1];
        }
        A.out[wordW(n, c, T)] = pack_half2(lo, hi);
    }
}

// Prep: pack x [32768,1024] fp32 -> fp16 pack. One float4 per thread.
__global__ void xpack_kernel(const float* __restrict__ X, uint32_t* __restrict__ out)
{
    const int K = 1024, T = 16;
    int idx = blockIdx.x * blockDim.x + threadIdx.x;
    int kc = idx & 255, r = idx >> 8;
    int k = kc * 4;
    float4 v = *(const float4*)&X[(size_t)r * K + k];
    size_t w0 = wordA(r, k, T);          // pair (k, k+1)
    out[w0]     = pack_half2(v.x, v.y);
    out[w0 + 4] = pack_half2(v.z, v.w);  // pair (k+2, k+3): t -> t+1 = +4 words
}

// ---------------------------------------------------------------------------
// Main GEMM: C = act(Apack @ Wpack^T + bias); emits fp16 pack of C.
// (exact 588us champion structure: two barriers per k-step)
// ---------------------------------------------------------------------------
__global__ __launch_bounds__(NTHREADS, 2)
void mma_layer_kernel(const uint32_t* __restrict__ Ap, const uint32_t* __restrict__ Wp,
                      const float* __restrict__ bias, float* __restrict__ C,
                      uint32_t* __restrict__ packOut,
                      int N, int T, int Tn, int KpadNext, int doRelu)
{
    extern __shared__ uint32_t dynsmem[];
    const uint32_t sbase = smem_u32(dynsmem);

    const int tid    = threadIdx.x;
    const int warp   = tid >> 5;
    const int lane   = tid & 31;
    const int warp_n = warp & 3;
    const int warp_m = warp >> 2;
    const int g      = lane >> 2;
    const int t      = lane & 3;
    const int mtile  = blockIdx.y;
    const int ntile  = blockIdx.x;
    const int m0     = mtile << 7;
    const int n0     = ntile << 7;

    const uint32_t* aSrc = Ap + ((size_t)mtile * T << 12);
    const uint32_t* wSrc = Wp + ((size_t)ntile * T << 12);

    float acc[4][4][4];
    #pragma unroll
    for (int i = 0; i < 4; i++)
        #pragma unroll
        for (int j = 0; j < 4; j++)
            #pragma unroll
            for (int q = 0; q < 4; q++) acc[i][j][q] = 0.f;

    auto issue = [&](int s, int kb) {
        uint32_t ab = sbase + (uint32_t)s * STAGE_BYTES;
        uint32_t wb = ab + 16384u;
        const uint32_t* a = aSrc + ((size_t)kb << 12);
        const uint32_t* w = wSrc + ((size_t)kb << 12);
        #pragma unroll
        for (int j = 0; j < 4; j++) {
            int o = tid + j * 256;
            cpa16(ab + o * 16u, a + o * 4);
            cpa16(wb + o * 16u, w + o * 4);
        }
        CPA_COMMIT();
    };

    issue(0, 0);
    if (T > 1) issue(1, 1);

    for (int kb = 0; kb < T; kb++) {
        CPA_WAIT1();
        __syncthreads();
        if (kb + 2 < T) issue((kb + 2) % 3, kb + 2);

        const int s = kb % 3;
        const uint32_t ab = sbase + (uint32_t)s * STAGE_BYTES;
        const uint32_t wb = ab + 16384u;

        #pragma unroll
        for (int kk = 0; kk < 4; kk++) {
            uint32_t a[4][4], b[4][2];
            #pragma unroll
            for (int mi = 0; mi < 4; mi++) {
                int frag = warp_m * 4 + mi;
                uint32_t addr = ab + (uint32_t)(((frag * 4 + kk) * 32 + lane) * 16);
                asm volatile("ld.shared.v4.u32 {%0,%1,%2,%3}, [%4];"
                             : "=r"(a[mi][0]), "=r"(a[mi][1]), "=r"(a[mi][2]), "=r"(a[mi][3])
                             : "r"(addr));
            }
            #pragma unroll
            for (int nj = 0; nj < 4; nj++) {
                int njg = warp_n * 4 + nj;
                uint32_t addr = wb + (uint32_t)((((njg * 4 + kk) * 32) + lane) * 8);
                asm volatile("ld.shared.v2.u32 {%0,%1}, [%2];"
                             : "=r"(b[nj][0]), "=r"(b[nj][1]) : "r"(addr));
            }
            #pragma unroll
            for (int mi = 0; mi < 4; mi++)
                #pragma unroll
                for (int nj = 0; nj < 4; nj++)
                    mma_f16(acc[mi][nj], a[mi][0], a[mi][1], a[mi][2], a[mi][3],
                            b[nj][0], b[nj][1]);
        }
        __syncthreads();
    }

    // ---- epilogue: bias + relu -> C (fp32), fp16 pack -> next layer ----
    #pragma unroll
    for (int mi = 0; mi < 4; mi++) {
        int r0 = m0 + warp_m * 64 + mi * 16 + g;
        #pragma unroll
        for (int nj = 0; nj < 4; nj++) {
            int cb = n0 + warp_n * 32 + nj * 8 + t * 2;
            float v0 = acc[mi][nj][0], v1 = acc[mi][nj][1];
            float v2 = acc[mi][nj][2], v3 = acc[mi][nj][3];
            if (cb < N) {     // N even -> cb+1 < N too
                float b0 = bias[cb], b1 = bias[cb + 1];
                v0 += b0; v1 += b1; v2 += b0; v3 += b1;
                if (doRelu) {
                    v0 = fmaxf(v0, 0.f); v1 = fmaxf(v1, 0.f);
                    v2 = fmaxf(v2, 0.f); v3 = fmaxf(v3, 0.f);
                }
                *(float2*)&C[(size_t)r0 * N + cb]       = make_float2(v0, v1);
                *(float2*)&C[(size_t)(r0 + 8) * N + cb] = make_float2(v2, v3);
            } else { v0 = v1 = v2 = v3 = 0.f; }
            if (packOut && cb < KpadNext) {
                packOut[wordA(r0,     cb, Tn)] = pack_half2(v0, v1);
                packOut[wordA(r0 + 8, cb, Tn)] = pack_half2(v2, v3);
            }
        }
    }
}

// ---------------------------------------------------------------------------
// Layer 5: [B,600] -> [B,6] GEMV. 512 threads = 16 warps = 16 rows/block;
// masked W5 prepacked in g_W5pack (no mask work, 2x less prep traffic).
// ---------------------------------------------------------------------------
__global__ __launch_bounds__(512)
void final_layer_kernel(const float* __restrict__ A, const float* __restrict__ bias,
                        float* __restrict__ O1, float* __restrict__ O2, int K)
{
    __shared__ float ws[3600];   // ws[k*6+n]
    const int tid = threadIdx.x;
    #pragma unroll
    for (int i = 0; i < 2; i++) {
        int idx = tid + i * 512;
        if (idx < 900) *(float4*)&ws[idx * 4] = *(const float4*)&g_W5pack[idx * 4];
    }
    __syncthreads();

    const int warp = tid >> 5, lane = tid & 31;
    const int row  = blockIdx.x * 16 + warp;
    const float* a = &A[(size_t)row * K];

    float acc[6] = {0.f, 0.f, 0.f, 0.f, 0.f, 0.f};
    for (int k = lane; k < K; k += 32) {
        float av = a[k];
        #pragma unroll
        for (int j = 0; j < 6; j++) acc[j] = fmaf(av, ws[k * 6 + j], acc[j]);
    }
    #pragma unroll
    for (int j = 0; j < 6; j++)
        #pragma unroll
        for (int o = 16; o > 0; o >>= 1)
            acc[j] += __shfl_xor_sync(0xffffffffu, acc[j], o);
    if (lane == 0) {
        #pragma unroll
        for (int j = 0; j < 6; j++) {
            float v = acc[j] + bias[j];
            O1[(size_t)row * 6 + j] = v;
            O2[(size_t)row * 6 + j] = v;
        }
    }
}

// ---------------------------------------------------------------------------
extern "C" void kernel_launch(void* const* d_in, const int* in_sizes, int n_in,
                              void* d_out, int out_size)
{
    (void)in_sizes; (void)n_in; (void)out_size;
    const int B = 32768;

    const float*    x  = (const float*)d_in[0];
    const float*    W1 = (const float*)d_in[1];
    const float*    b1 = (const float*)d_in[2];
    const uint32_t* m1 = (const uint32_t*)d_in[3];
    const float*    W2 = (const float*)d_in[4];
    const float*    b2 = (const float*)d_in[5];
    const uint32_t* m2 = (const uint32_t*)d_in[6];
    const float*    W3 = (const float*)d_in[7];
    const float*    b3 = (const float*)d_in[8];
    const uint32_t* m3 = (const uint32_t*)d_in[9];
    const float*    W4 = (const float*)d_in[10];
    const float*    b4 = (const float*)d_in[11];
    const uint32_t* m4 = (const uint32_t*)d_in[12];
    const float*    W5 = (const float*)d_in[13];
    const float*    b5 = (const float*)d_in[14];
    const uint32_t* m5 = (const uint32_t*)d_in[15];

    float* out = (float*)d_out;
    float* h5a = out;                    // [B,6]
    float* h1  = out + (size_t)B * 6;    // [B,1000]
    float* h2  = h1  + (size_t)B * 1000; // [B,800]
    float* h3  = h2  + (size_t)B * 800;  // [B,400]
    float* h4  = h3  + (size_t)B * 400;  // [B,600]
    float* h5b = h4  + (size_t)B * 600;  // [B,6]

    uint32_t *ap0, *ap1, *wp;
    cudaGetSymbolAddress((void**)&ap0, g_Apack0);
    cudaGetSymbolAddress((void**)&ap1, g_Apack1);
    cudaGetSymbolAddress((void**)&wp,  g_Wpack);

    static bool attrDone = false;
    if (!attrDone) {
        cudaFuncSetAttribute(mma_layer_kernel, cudaFuncAttributeMaxDynamicSharedMemorySize, SMEM_REQ);
        attrDone = true;
    }

    // ---- prep: pack all weights (incl. W5) in ONE launch, then x ----
    WArgs wa1 = { W1, m1, wp + WOFF1, 1000, 1024, 1024, 8 };
    WArgs wa2 = { W2, m2, wp + WOFF2,  800, 1000, 1024, 7 };
    WArgs wa3 = { W3, m3, wp + WOFF3,  400,  800,  832, 4 };
    WArgs wa4 = { W4, m4, wp + WOFF4,  600,  400,  448, 5 };
    wpack_all_kernel<<<dim3(384, 5), 256>>>(wa1, wa2, wa3, wa4, W5, m5);
    xpack_kernel<<<B, 256>>>(x, ap0);

    dim3 blk(NTHREADS);
    const int SM = SMEM_REQ;
    // L1: Kpad=1024 (T=16) -> h1 [B,1000]; pack -> ap1 (KpadNext=1024, Tn=16)
    mma_layer_kernel<<<dim3(8, B/128), blk, SM>>>(ap0, wp + WOFF1, b1, h1, ap1, 1000, 16, 16, 1024, 1);
    // L2: Kpad=1024 (T=16) -> h2 [B,800]; pack -> ap0 (KpadNext=832, Tn=13)
    mma_layer_kernel<<<dim3(7, B/128), blk, SM>>>(ap1, wp + WOFF2, b2, h2, ap0,  800, 16, 13,  832, 1);
    // L3: Kpad=832 (T=13) -> h3 [B,400]; pack -> ap1 (KpadNext=448, Tn=7)
    mma_layer_kernel<<<dim3(4, B/128), blk, SM>>>(ap0, wp + WOFF3, b3, h3, ap1,  400, 13,  7,  448, 1);
    // L4: Kpad=448 (T=7) -> h4 [B,600]; no pack, no relu
    mma_layer_kernel<<<dim3(5, B/128), blk, SM>>>(ap1, wp + WOFF4, b4, h4, (uint32_t*)0, 600, 7, 0, 0, 0);
    // L5 GEMV (prepacked W5)
    final_layer_kernel<<<B/16, 512>>>(h4, b5, h5a, h5b, 600);
}